// round 15
// baseline (speedup 1.0000x reference)
#include <cuda_runtime.h>
#include <math.h>

// Problem constants
#define B   4
#define T   10
#define CIN 64
#define CO  64          // Cout
#define H   96
#define W   96
#define HW  (H*W)
#define L   5

// ---------------------------------------------------------------------------
// Scratch (device globals — no allocation allowed). g_zero is never written,
// so it stays zero across graph replays (module-load zero init).
// ---------------------------------------------------------------------------
__device__ float g_i2h[(size_t)B*T*3*CO*HW];    // 283 MB
__device__ float g_i2f[(size_t)B*T*32*HW];      //  47 MB
__device__ float g_f1[(size_t)B*32*HW];
__device__ float g_flows[(size_t)B*2*L*HW];
__device__ float g_warped[(size_t)B*L*CO*HW];   //  47 MB
__device__ float g_zero[(size_t)B*CO*HW];       // stays zero

// ---------------------------------------------------------------------------
// Direct conv, KxK, pad=K/2, stride 1. Software-pipelined (double-buffered
// smem tiles, prefetch ci+2 into registers while computing ci).
// Tile: 32x8 output pixels per 128-thread subgroup (tx=lt&31, ty=lt>>5;
// each thread does rows ty and ty+4). A warp's input LDS covers 32
// CONSECUTIVE floats -> 32 distinct banks -> 1 phase (the old 16x16 tile
// had a guaranteed 2-way conflict from the SW-row-offset wraparound).
// CO_T output channels per subgroup in registers; weight LDS is a uniform
// broadcast (1 phase). CSPLIT subgroups split Cin; smem reduction.
// FUSE: out = tanh(conv + bias + addbuf)   (for f1 = tanh(i2f + h2f))
// Image index m = nBase + (blockIdx.z/coG)*nStep  (chunked launches).
// ---------------------------------------------------------------------------
template<int K, int CO_T, bool FUSE, int CSPLIT>
__global__ __launch_bounds__(128*CSPLIT)
void conv2d_k(const float* __restrict__ in, int inBS,
              const float* __restrict__ w, const float* __restrict__ bias,
              const float* __restrict__ addb, int addBS,
              float* __restrict__ out, int outBS,
              int Cin, int Cout, int nBase, int nStep)
{
    constexpr int PAD = K/2;
    constexpr int TW = 32, TH = 8;
    constexpr int SW = TW + K - 1, SH = TH + K - 1;
    constexpr int SIN = SH*SW;
    constexpr int NIN = (SIN + 127)/128;
    constexpr int SWT = CO_T*K*K;
    constexpr int NWT = (SWT + 127)/128;

    __shared__ float s_in[CSPLIT][2][SIN];
    __shared__ float s_w [CSPLIT][2][SWT];
    __shared__ float s_red[(CSPLIT > 1) ? (128*2*CO_T) : 1];

    const int coG = Cout / CO_T;
    const int n   = nBase + (blockIdx.z / coG) * nStep;
    const int g   = blockIdx.z % coG;
    const int sub = threadIdx.x >> 7;
    const int lt  = threadIdx.x & 127;
    const int tx  = lt & 31;
    const int ty  = lt >> 5;                 // 0..3
    const int gx0 = blockIdx.x * TW;
    const int gy0 = blockIdx.y * TH;
    const int cinPer = Cin / CSPLIT;

    const float* inb = in + (size_t)n*inBS + (size_t)(sub*cinPer)*HW;
    const float* wb  = w  + ((size_t)(g*CO_T)*Cin + (size_t)(sub*cinPer))*(K*K);

    // per-thread cooperative-load descriptors (constant across ci)
    int  ioff[NIN]; bool ival[NIN];
#pragma unroll
    for (int j = 0; j < NIN; j++) {
        int i = lt + j*128;
        int sy = i / SW, sx = i - sy*SW;
        int gy = gy0 + sy - PAD, gx = gx0 + sx - PAD;
        bool ok = (i < SIN) && gy >= 0 && gy < H && gx >= 0 && gx < W;
        ival[j] = ok;
        ioff[j] = ok ? gy*W + gx : 0;
    }
    int woff[NWT];
#pragma unroll
    for (int j = 0; j < NWT; j++) {
        int i = lt + j*128;
        int co = i / (K*K), tp = i - co*(K*K);
        woff[j] = (i < SWT) ? co*Cin*(K*K) + tp : 0;
    }

    float acc0[CO_T], acc1[CO_T];
#pragma unroll
    for (int c = 0; c < CO_T; c++) { acc0[c] = 0.f; acc1[c] = 0.f; }

    float rin[NIN], rwt[NWT];

    // prologue: load ci=0 -> buf0; prefetch ci=1 into registers
#pragma unroll
    for (int j = 0; j < NIN; j++) rin[j] = ival[j] ? __ldg(inb + ioff[j]) : 0.f;
#pragma unroll
    for (int j = 0; j < NWT; j++) rwt[j] = __ldg(wb + woff[j]);
#pragma unroll
    for (int j = 0; j < NIN; j++) { int i = lt + j*128; if (i < SIN) s_in[sub][0][i] = rin[j]; }
#pragma unroll
    for (int j = 0; j < NWT; j++) { int i = lt + j*128; if (i < SWT) s_w[sub][0][i]  = rwt[j]; }
    if (cinPer > 1) {
#pragma unroll
        for (int j = 0; j < NIN; j++) rin[j] = ival[j] ? __ldg(inb + HW + ioff[j]) : 0.f;
#pragma unroll
        for (int j = 0; j < NWT; j++) rwt[j] = __ldg(wb + (K*K) + woff[j]);
    }
    __syncthreads();

    int p = 0;
    for (int ci = 0; ci < cinPer; ci++) {
        const float* si = s_in[sub][p];
        const float* sw = s_w[sub][p];
#pragma unroll
        for (int ky = 0; ky < K; ky++) {
#pragma unroll
            for (int kx = 0; kx < K; kx++) {
                float iv0 = si[(ty     + ky)*SW + tx + kx];
                float iv1 = si[(ty + 4 + ky)*SW + tx + kx];
                int tap = ky*K + kx;
#pragma unroll
                for (int c = 0; c < CO_T; c++) {
                    float wv = sw[c*(K*K) + tap];   // warp-uniform -> broadcast
                    acc0[c] += iv0 * wv;
                    acc1[c] += iv1 * wv;
                }
            }
        }
        if (ci + 1 < cinPer) {
            // commit prefetched ci+1 to the other buffer (LDG already in flight)
#pragma unroll
            for (int j = 0; j < NIN; j++) { int i = lt + j*128; if (i < SIN) s_in[sub][p^1][i] = rin[j]; }
#pragma unroll
            for (int j = 0; j < NWT; j++) { int i = lt + j*128; if (i < SWT) s_w[sub][p^1][i]  = rwt[j]; }
            if (ci + 2 < cinPer) {
                const float* ib2 = inb + (size_t)(ci + 2)*HW;
                const float* wb2 = wb + (ci + 2)*(K*K);
#pragma unroll
                for (int j = 0; j < NIN; j++) rin[j] = ival[j] ? __ldg(ib2 + ioff[j]) : 0.f;
#pragma unroll
                for (int j = 0; j < NWT; j++) rwt[j] = __ldg(wb2 + woff[j]);
            }
        }
        __syncthreads();
        p ^= 1;
    }

    // Cin-split reduction (conflict-free: lane-contiguous layout)
    if (CSPLIT > 1) {
        for (int s = 1; s < CSPLIT; s++) {
            if (sub == s) {
#pragma unroll
                for (int c = 0; c < CO_T; c++) {
                    s_red[c*128 + lt]          = acc0[c];
                    s_red[(CO_T + c)*128 + lt] = acc1[c];
                }
            }
            __syncthreads();
            if (sub == 0) {
#pragma unroll
                for (int c = 0; c < CO_T; c++) {
                    acc0[c] += s_red[c*128 + lt];
                    acc1[c] += s_red[(CO_T + c)*128 + lt];
                }
            }
            __syncthreads();
        }
        if (sub != 0) return;
    }

    // epilogue
    const int x = gx0 + tx, y = gy0 + ty;
    const int p0 = y*W + x, p1 = p0 + 4*W;
#pragma unroll
    for (int c = 0; c < CO_T; c++) {
        int gc = g*CO_T + c;
        float bv = bias[gc];
        float v0 = acc0[c] + bv;
        float v1 = acc1[c] + bv;
        size_t ob = (size_t)n*outBS + (size_t)gc*HW;
        if (FUSE) {
            size_t ab = (size_t)n*addBS + (size_t)gc*HW;
            v0 = tanhf(v0 + addb[ab + p0]);
            v1 = tanhf(v1 + addb[ab + p1]);
        }
        out[ob + p0] = v0;
        out[ob + p1] = v1;
    }
}

// ---------------------------------------------------------------------------
// Bilinear warp: warped[b, l*CO+c, y, x] = sample(prev_h[b,c], pos - flows[b,l])
// Matches reference fp32 op order; per-corner validity folded into weights.
// ---------------------------------------------------------------------------
__global__ void warp_k(const float* __restrict__ prevh, int phBS,
                       const float* __restrict__ flows,
                       float* __restrict__ warped)
{
    int i = blockIdx.x * blockDim.x + threadIdx.x;
    if (i >= B*L*HW) return;
    int pix = i % HW;
    int bl  = i / HW;
    int l   = bl % L;
    int b   = bl / L;
    int x = pix % W, y = pix / W;

    float flx = flows[((size_t)(b*L + l)*2 + 0)*HW + pix];
    float fly = flows[((size_t)(b*L + l)*2 + 1)*HW + pix];

    // flow passed to _warp is -flows[:,l]
    float nx = 2.0f*((float)x - flx)/(float)(W-1) - 1.0f;
    float ny = 2.0f*((float)y - fly)/(float)(H-1) - 1.0f;
    float fx = (nx + 1.0f)*((float)W*0.5f) - 0.5f;
    float fy = (ny + 1.0f)*((float)H*0.5f) - 0.5f;

    float x0f = floorf(fx), y0f = floorf(fy);
    float wx = fx - x0f, wy = fy - y0f;
    int x0 = (int)x0f, y0 = (int)y0f;
    int x1 = x0 + 1,   y1 = y0 + 1;

    float vx0 = (x0 >= 0 && x0 < W) ? 1.f : 0.f;
    float vx1 = (x1 >= 0 && x1 < W) ? 1.f : 0.f;
    float vy0 = (y0 >= 0 && y0 < H) ? 1.f : 0.f;
    float vy1 = (y1 >= 0 && y1 < H) ? 1.f : 0.f;
    int cx0 = min(max(x0,0),W-1), cx1 = min(max(x1,0),W-1);
    int cy0 = min(max(y0,0),H-1), cy1 = min(max(y1,0),H-1);

    float w00 = (1.f-wx)*(1.f-wy)*vx0*vy0;
    float w01 = wx      *(1.f-wy)*vx1*vy0;
    float w10 = (1.f-wx)*wy      *vx0*vy1;
    float w11 = wx      *wy      *vx1*vy1;
    int o00 = cy0*W + cx0, o01 = cy0*W + cx1;
    int o10 = cy1*W + cx0, o11 = cy1*W + cx1;

    const float* hb = prevh + (size_t)b*phBS;
    float* ob = warped + ((size_t)b*(L*CO) + (size_t)l*CO)*HW + pix;
#pragma unroll 4
    for (int c = 0; c < CO; c++) {
        const float* hc = hb + (size_t)c*HW;
        float v = w00*hc[o00] + w01*hc[o01] + w10*hc[o10] + w11*hc[o11];
        ob[(size_t)c*HW] = v;
    }
}

// ---------------------------------------------------------------------------
// Fused: h2h = 1x1 conv(warped, ret_w) + ret_b, then GRU gates, write nh.
// 16x16 pixel tile, 128 threads (2 px/thread), 8 matched (r,u,m) channel
// triples per block. Inputs streamed with 16-deep LDG batches (MLP).
// ---------------------------------------------------------------------------
__global__ __launch_bounds__(128)
void gate_k(const float* __restrict__ warped,
            const float* __restrict__ retw,
            const float* __restrict__ retb,
            const float* __restrict__ i2ht,   // base = g_i2h + (t*B)*192*HW (scrambled idx!)
            const float* __restrict__ prevh, int phBS,
            float* __restrict__ outb, int outBS)
{
    __shared__ float s_w[320*24];
    const int b = blockIdx.z >> 3;
    const int g = blockIdx.z & 7;
    const int tx = threadIdx.x & 15;
    const int ty = threadIdx.x >> 4;
    const int x = blockIdx.x*16 + tx;
    const int y = blockIdx.y*16 + ty;

    for (int i = threadIdx.x; i < 320*24; i += 128) {
        int ci = i / 24, j = i - ci*24;
        int co = (j >> 3)*64 + g*8 + (j & 7);   // j<8: r-set, j<16: u-set, else m-set
        s_w[i] = retw[(size_t)co*320 + ci];
    }
    __syncthreads();

    float acc0[24], acc1[24];
#pragma unroll
    for (int j = 0; j < 24; j++){ acc0[j] = 0.f; acc1[j] = 0.f; }

    const int p0 = y*W + x, p1 = p0 + 8*W;
    const float* wp = warped + (size_t)b*(320*HW);
    for (int ci0 = 0; ci0 < 320; ci0 += 8) {
        float v0[8], v1[8];
#pragma unroll
        for (int q = 0; q < 8; q++) {
            v0[q] = __ldg(wp + (size_t)(ci0+q)*HW + p0);
            v1[q] = __ldg(wp + (size_t)(ci0+q)*HW + p1);
        }
#pragma unroll
        for (int q = 0; q < 8; q++) {
            const float* wr = s_w + (ci0+q)*24;
#pragma unroll
            for (int j = 0; j < 24; j++) {
                float wv = wr[j];               // warp-uniform -> broadcast
                acc0[j] += v0[q]*wv;
                acc1[j] += v1[q]*wv;
            }
        }
    }

    const float* ib = i2ht  + (size_t)b*(192*HW);
    const float* ph = prevh + (size_t)b*phBS;
    float* ob = outb + (size_t)b*outBS;

#pragma unroll
    for (int i = 0; i < 8; i++) {
        int co = g*8 + i;
        float br = retb[co], bu = retb[64+co], bm = retb[128+co];
        {   // pixel 0
            float hr = acc0[i] + br, hu = acc0[8+i] + bu, hm = acc0[16+i] + bm;
            float r = 1.f/(1.f + expf(-(ib[(size_t)co*HW       + p0] + hr)));
            float u = 1.f/(1.f + expf(-(ib[(size_t)(64+co)*HW  + p0] + hu)));
            float m = tanhf(        ib[(size_t)(128+co)*HW + p0] + r*hm);
            float pv = ph[(size_t)co*HW + p0];
            ob[(size_t)co*HW + p0] = u*pv + (1.f - u)*m;
        }
        {   // pixel 1
            float hr = acc1[i] + br, hu = acc1[8+i] + bu, hm = acc1[16+i] + bm;
            float r = 1.f/(1.f + expf(-(ib[(size_t)co*HW       + p1] + hr)));
            float u = 1.f/(1.f + expf(-(ib[(size_t)(64+co)*HW  + p1] + hu)));
            float m = tanhf(        ib[(size_t)(128+co)*HW + p1] + r*hm);
            float pv = ph[(size_t)co*HW + p1];
            ob[(size_t)co*HW + p1] = u*pv + (1.f - u)*m;
        }
    }
}

// last_h = outs[:, T-1]
__global__ void copy_last(float* __restrict__ out)
{
    int i = blockIdx.x*blockDim.x + threadIdx.x;
    if (i >= B*CO*HW) return;
    int b = i / (CO*HW);
    int r = i - b*(CO*HW);
    out[(size_t)B*T*CO*HW + i] = out[((size_t)(b*T + (T-1))*CO)*HW + r];
}

// ---------------------------------------------------------------------------
extern "C" void kernel_launch(void* const* d_in, const int* in_sizes, int n_in,
                              void* d_out, int out_size)
{
    const float* inputs  = (const float*)d_in[0];
    const float* i2h_w   = (const float*)d_in[1];
    const float* i2h_b   = (const float*)d_in[2];
    const float* i2f_w   = (const float*)d_in[3];
    const float* i2f_b   = (const float*)d_in[4];
    const float* h2f_w   = (const float*)d_in[5];
    const float* h2f_b   = (const float*)d_in[6];
    const float* flows_w = (const float*)d_in[7];
    const float* flows_b = (const float*)d_in[8];
    const float* ret_w   = (const float*)d_in[9];
    const float* ret_b   = (const float*)d_in[10];
    float* out = (float*)d_out;
    (void)in_sizes; (void)n_in; (void)out_size;

    float *p_i2h, *p_i2f, *p_f1, *p_flows, *p_warped, *p_zero;
    cudaGetSymbolAddress((void**)&p_i2h,    g_i2h);
    cudaGetSymbolAddress((void**)&p_i2f,    g_i2f);
    cudaGetSymbolAddress((void**)&p_f1,     g_f1);
    cudaGetSymbolAddress((void**)&p_flows,  g_flows);
    cudaGetSymbolAddress((void**)&p_warped, g_warped);
    cudaGetSymbolAddress((void**)&p_zero,   g_zero);

    // One-time host resources (streams/events, no device memory). Device work
    // per call is identical and deterministic.
    static cudaStream_t s2 = nullptr;
    static cudaEvent_t  evFork = nullptr;
    static cudaEvent_t  evI2f[T], evI2h[T];
    static bool ok2 = false;
    if (s2 == nullptr) {
        bool good = (cudaStreamCreateWithFlags(&s2, cudaStreamNonBlocking) == cudaSuccess);
        good = good && (cudaEventCreateWithFlags(&evFork, cudaEventDisableTiming) == cudaSuccess);
        for (int t = 0; t < T && good; t++) {
            good = good && (cudaEventCreateWithFlags(&evI2f[t], cudaEventDisableTiming) == cudaSuccess);
            good = good && (cudaEventCreateWithFlags(&evI2h[t], cudaEventDisableTiming) == cudaSuccess);
        }
        ok2 = good;
    }

    cudaStream_t sp = 0;   // precompute stream (forked if available)
    if (ok2) {
        cudaEventRecord(evFork, 0);
        cudaStreamWaitEvent(s2, evFork, 0);
        sp = s2;
    }

    // Precompute, chunked per consumer timestep, on the forked stream.
    //  i2f chunk t: images m = b*T + t  (consumed by h2f at step t)
    //  i2h chunk t: images m = t*B + b  (consumed by gate at step t; this IS
    //               the reference's reshape(B*T)->reshape(T,B) scramble)
    // Tile grid: x = 96/32 = 3, y = 96/8 = 12.
    for (int t = 0; t < T; t++) {
        conv2d_k<5,16,false,1><<<dim3(3,12,B*2), 128, 0, sp>>>(
            inputs, CIN*HW, i2f_w, i2f_b, nullptr, 0,
            p_i2f, 32*HW, CIN, 32, /*nBase=*/t, /*nStep=*/T);
        if (ok2) cudaEventRecord(evI2f[t], s2);

        conv2d_k<3,16,false,1><<<dim3(3,12,B*12), 128, 0, sp>>>(
            inputs, CIN*HW, i2h_w, i2h_b, nullptr, 0,
            p_i2h, 3*CO*HW, CIN, 3*CO, /*nBase=*/t*B, /*nStep=*/1);
        if (ok2) cudaEventRecord(evI2h[t], s2);
    }

    for (int t = 0; t < T; t++) {
        const float* prevh = (t == 0) ? p_zero : out + (size_t)(t-1)*CO*HW;
        int phBS = (t == 0) ? CO*HW : T*CO*HW;

        if (ok2) cudaStreamWaitEvent(0, evI2f[t], 0);

        // f1 = tanh(i2f[b,t] + conv5x5(prev_h, h2f_w) + h2f_b)   [Cin split x2]
        conv2d_k<5,16,true,2><<<dim3(3,12,B*2), 256>>>(
            prevh, phBS, h2f_w, h2f_b,
            p_i2f + (size_t)t*32*HW, T*32*HW,
            p_f1, 32*HW, CO, 32, 0, 1);

        // flows = conv5x5(f1, flows_w) + flows_b   -> (B, L*2, H, W)  [Cin split x4]
        conv2d_k<5,10,false,4><<<dim3(3,12,B), 512>>>(
            p_f1, 32*HW, flows_w, flows_b, nullptr, 0,
            p_flows, 2*L*HW, 32, 2*L, 0, 1);

        // warped(B, L*CO, H, W)
        warp_k<<<(B*L*HW + 255)/256, 256>>>(prevh, phBS, p_flows, p_warped);

        if (ok2) cudaStreamWaitEvent(0, evI2h[t], 0);

        // h2h (1x1, 320->192) + GRU gates -> nh written to out[:, t]
        gate_k<<<dim3(6,6,B*8), 128>>>(
            p_warped, ret_w, ret_b,
            p_i2h + (size_t)(t*B)*3*CO*HW,
            prevh, phBS,
            out + (size_t)t*CO*HW, T*CO*HW);
    }

    copy_last<<<(B*CO*HW + 255)/256, 256>>>(out);
}

// round 16
// speedup vs baseline: 1.0151x; 1.0151x over previous
#include <cuda_runtime.h>
#include <math.h>

// Problem constants
#define B   4
#define T   10
#define CIN 64
#define CO  64          // Cout
#define H   96
#define W   96
#define HW  (H*W)
#define L   5

// ---------------------------------------------------------------------------
// Scratch (device globals — no allocation allowed). g_zero is never written,
// so it stays zero across graph replays (module-load zero init).
// ---------------------------------------------------------------------------
__device__ float g_i2h[(size_t)B*T*3*CO*HW];    // 283 MB
__device__ float g_i2f[(size_t)B*T*32*HW];      //  47 MB
__device__ float g_f1[(size_t)B*32*HW];
__device__ float g_flows[(size_t)B*2*L*HW];
__device__ float g_warped[(size_t)B*L*CO*HW];   //  47 MB
__device__ float g_zero[(size_t)B*CO*HW];       // stays zero

// ---------------------------------------------------------------------------
// Direct conv, KxK, pad=K/2, stride 1. Software-pipelined (double-buffered
// smem tiles, prefetch ci+2 into registers while computing ci).
// Tile: 32x8 output pixels per 128-thread subgroup (tx=lt&31, ty=lt>>5;
// rows ty, ty+4). Warp input LDS = 32 consecutive floats -> 1 phase.
// WEIGHTS stored TRANSPOSED in smem: s_w[tap*CO_T + co] (channels contiguous)
// and read as float4/float2 BROADCASTS -> 4x/2x fewer crossbar slots.
// Per-ci LDS:FMA cycle ratio (K=3,CO_T=16): (18+36)/144 -> fma-bound.
// CSPLIT subgroups split Cin; smem reduction. FUSE: out=tanh(conv+bias+addb).
// Image index m = nBase + (blockIdx.z/coG)*nStep  (chunked launches).
// ---------------------------------------------------------------------------
template<int K, int CO_T, bool FUSE, int CSPLIT>
__global__ __launch_bounds__(128*CSPLIT)
void conv2d_k(const float* __restrict__ in, int inBS,
              const float* __restrict__ w, const float* __restrict__ bias,
              const float* __restrict__ addb, int addBS,
              float* __restrict__ out, int outBS,
              int Cin, int Cout, int nBase, int nStep)
{
    constexpr int PAD = K/2;
    constexpr int TW = 32, TH = 8;
    constexpr int SW = TW + K - 1, SH = TH + K - 1;
    constexpr int SIN = SH*SW;
    constexpr int NIN = (SIN + 127)/128;
    constexpr int KK  = K*K;
    constexpr int SWT = CO_T*KK;
    constexpr int NWT = (SWT + 127)/128;
    constexpr bool V4 = (CO_T % 4 == 0);

    __shared__ __align__(16) float s_in[CSPLIT][2][SIN];
    __shared__ __align__(16) float s_w [CSPLIT][2][SWT];
    __shared__ __align__(16) float s_red[(CSPLIT > 1) ? (128*2*CO_T) : 1];

    const int coG = Cout / CO_T;
    const int n   = nBase + (blockIdx.z / coG) * nStep;
    const int g   = blockIdx.z % coG;
    const int sub = threadIdx.x >> 7;
    const int lt  = threadIdx.x & 127;
    const int tx  = lt & 31;
    const int ty  = lt >> 5;                 // 0..3
    const int gx0 = blockIdx.x * TW;
    const int gy0 = blockIdx.y * TH;
    const int cinPer = Cin / CSPLIT;

    const float* inb = in + (size_t)n*inBS + (size_t)(sub*cinPer)*HW;
    const float* wb  = w  + ((size_t)(g*CO_T)*Cin + (size_t)(sub*cinPer))*KK;

    // per-thread cooperative-load descriptors (constant across ci)
    int  ioff[NIN]; bool ival[NIN];
#pragma unroll
    for (int j = 0; j < NIN; j++) {
        int i = lt + j*128;
        int sy = i / SW, sx = i - sy*SW;
        int gy = gy0 + sy - PAD, gx = gx0 + sx - PAD;
        bool ok = (i < SIN) && gy >= 0 && gy < H && gx >= 0 && gx < W;
        ival[j] = ok;
        ioff[j] = ok ? gy*W + gx : 0;
    }
    // weight staging is TRANSPOSED: smem index i = tap*CO_T + co
    int woff[NWT];
#pragma unroll
    for (int j = 0; j < NWT; j++) {
        int i = lt + j*128;
        int co = i % CO_T, tap = i / CO_T;
        woff[j] = (i < SWT) ? co*Cin*KK + tap : 0;
    }

    float acc0[CO_T], acc1[CO_T];
#pragma unroll
    for (int c = 0; c < CO_T; c++) { acc0[c] = 0.f; acc1[c] = 0.f; }

    float rin[NIN], rwt[NWT];

    // prologue: load ci=0 -> buf0; prefetch ci=1 into registers
#pragma unroll
    for (int j = 0; j < NIN; j++) rin[j] = ival[j] ? __ldg(inb + ioff[j]) : 0.f;
#pragma unroll
    for (int j = 0; j < NWT; j++) rwt[j] = __ldg(wb + woff[j]);
#pragma unroll
    for (int j = 0; j < NIN; j++) { int i = lt + j*128; if (i < SIN) s_in[sub][0][i] = rin[j]; }
#pragma unroll
    for (int j = 0; j < NWT; j++) { int i = lt + j*128; if (i < SWT) s_w[sub][0][i]  = rwt[j]; }
    if (cinPer > 1) {
#pragma unroll
        for (int j = 0; j < NIN; j++) rin[j] = ival[j] ? __ldg(inb + HW + ioff[j]) : 0.f;
#pragma unroll
        for (int j = 0; j < NWT; j++) rwt[j] = __ldg(wb + KK + woff[j]);
    }
    __syncthreads();

    int p = 0;
    for (int ci = 0; ci < cinPer; ci++) {
        const float* si = s_in[sub][p];
        const float* sw = s_w[sub][p];
#pragma unroll
        for (int ky = 0; ky < K; ky++) {
#pragma unroll
            for (int kx = 0; kx < K; kx++) {
                float iv0 = si[(ty     + ky)*SW + tx + kx];
                float iv1 = si[(ty + 4 + ky)*SW + tx + kx];
                int tap = ky*K + kx;
                if (V4) {
                    const float4* w4 = reinterpret_cast<const float4*>(sw + tap*CO_T);
#pragma unroll
                    for (int c4 = 0; c4 < CO_T/4; c4++) {
                        float4 wv = w4[c4];        // 16B broadcast, 1 slot
                        acc0[4*c4+0] += iv0 * wv.x;  acc1[4*c4+0] += iv1 * wv.x;
                        acc0[4*c4+1] += iv0 * wv.y;  acc1[4*c4+1] += iv1 * wv.y;
                        acc0[4*c4+2] += iv0 * wv.z;  acc1[4*c4+2] += iv1 * wv.z;
                        acc0[4*c4+3] += iv0 * wv.w;  acc1[4*c4+3] += iv1 * wv.w;
                    }
                } else {
                    const float2* w2 = reinterpret_cast<const float2*>(sw + tap*CO_T);
#pragma unroll
                    for (int c2 = 0; c2 < CO_T/2; c2++) {
                        float2 wv = w2[c2];        // 8B broadcast, 1 slot
                        acc0[2*c2+0] += iv0 * wv.x;  acc1[2*c2+0] += iv1 * wv.x;
                        acc0[2*c2+1] += iv0 * wv.y;  acc1[2*c2+1] += iv1 * wv.y;
                    }
                }
            }
        }
        if (ci + 1 < cinPer) {
            // commit prefetched ci+1 to the other buffer (LDG already in flight)
#pragma unroll
            for (int j = 0; j < NIN; j++) { int i = lt + j*128; if (i < SIN) s_in[sub][p^1][i] = rin[j]; }
#pragma unroll
            for (int j = 0; j < NWT; j++) { int i = lt + j*128; if (i < SWT) s_w[sub][p^1][i]  = rwt[j]; }
            if (ci + 2 < cinPer) {
                const float* ib2 = inb + (size_t)(ci + 2)*HW;
                const float* wb2 = wb + (ci + 2)*KK;
#pragma unroll
                for (int j = 0; j < NIN; j++) rin[j] = ival[j] ? __ldg(ib2 + ioff[j]) : 0.f;
#pragma unroll
                for (int j = 0; j < NWT; j++) rwt[j] = __ldg(wb2 + woff[j]);
            }
        }
        __syncthreads();
        p ^= 1;
    }

    // Cin-split reduction (conflict-free: lane-contiguous layout)
    if (CSPLIT > 1) {
        for (int s = 1; s < CSPLIT; s++) {
            if (sub == s) {
#pragma unroll
                for (int c = 0; c < CO_T; c++) {
                    s_red[c*128 + lt]          = acc0[c];
                    s_red[(CO_T + c)*128 + lt] = acc1[c];
                }
            }
            __syncthreads();
            if (sub == 0) {
#pragma unroll
                for (int c = 0; c < CO_T; c++) {
                    acc0[c] += s_red[c*128 + lt];
                    acc1[c] += s_red[(CO_T + c)*128 + lt];
                }
            }
            __syncthreads();
        }
        if (sub != 0) return;
    }

    // epilogue
    const int x = gx0 + tx, y = gy0 + ty;
    const int p0 = y*W + x, p1 = p0 + 4*W;
#pragma unroll
    for (int c = 0; c < CO_T; c++) {
        int gc = g*CO_T + c;
        float bv = bias[gc];
        float v0 = acc0[c] + bv;
        float v1 = acc1[c] + bv;
        size_t ob = (size_t)n*outBS + (size_t)gc*HW;
        if (FUSE) {
            size_t ab = (size_t)n*addBS + (size_t)gc*HW;
            v0 = tanhf(v0 + addb[ab + p0]);
            v1 = tanhf(v1 + addb[ab + p1]);
        }
        out[ob + p0] = v0;
        out[ob + p1] = v1;
    }
}

// ---------------------------------------------------------------------------
// Bilinear warp: warped[b, l*CO+c, y, x] = sample(prev_h[b,c], pos - flows[b,l])
// Matches reference fp32 op order; per-corner validity folded into weights.
// ---------------------------------------------------------------------------
__global__ void warp_k(const float* __restrict__ prevh, int phBS,
                       const float* __restrict__ flows,
                       float* __restrict__ warped)
{
    int i = blockIdx.x * blockDim.x + threadIdx.x;
    if (i >= B*L*HW) return;
    int pix = i % HW;
    int bl  = i / HW;
    int l   = bl % L;
    int b   = bl / L;
    int x = pix % W, y = pix / W;

    float flx = flows[((size_t)(b*L + l)*2 + 0)*HW + pix];
    float fly = flows[((size_t)(b*L + l)*2 + 1)*HW + pix];

    // flow passed to _warp is -flows[:,l]
    float nx = 2.0f*((float)x - flx)/(float)(W-1) - 1.0f;
    float ny = 2.0f*((float)y - fly)/(float)(H-1) - 1.0f;
    float fx = (nx + 1.0f)*((float)W*0.5f) - 0.5f;
    float fy = (ny + 1.0f)*((float)H*0.5f) - 0.5f;

    float x0f = floorf(fx), y0f = floorf(fy);
    float wx = fx - x0f, wy = fy - y0f;
    int x0 = (int)x0f, y0 = (int)y0f;
    int x1 = x0 + 1,   y1 = y0 + 1;

    float vx0 = (x0 >= 0 && x0 < W) ? 1.f : 0.f;
    float vx1 = (x1 >= 0 && x1 < W) ? 1.f : 0.f;
    float vy0 = (y0 >= 0 && y0 < H) ? 1.f : 0.f;
    float vy1 = (y1 >= 0 && y1 < H) ? 1.f : 0.f;
    int cx0 = min(max(x0,0),W-1), cx1 = min(max(x1,0),W-1);
    int cy0 = min(max(y0,0),H-1), cy1 = min(max(y1,0),H-1);

    float w00 = (1.f-wx)*(1.f-wy)*vx0*vy0;
    float w01 = wx      *(1.f-wy)*vx1*vy0;
    float w10 = (1.f-wx)*wy      *vx0*vy1;
    float w11 = wx      *wy      *vx1*vy1;
    int o00 = cy0*W + cx0, o01 = cy0*W + cx1;
    int o10 = cy1*W + cx0, o11 = cy1*W + cx1;

    const float* hb = prevh + (size_t)b*phBS;
    float* ob = warped + ((size_t)b*(L*CO) + (size_t)l*CO)*HW + pix;
#pragma unroll 4
    for (int c = 0; c < CO; c++) {
        const float* hc = hb + (size_t)c*HW;
        float v = w00*hc[o00] + w01*hc[o01] + w10*hc[o10] + w11*hc[o11];
        ob[(size_t)c*HW] = v;
    }
}

// ---------------------------------------------------------------------------
// Fused: h2h = 1x1 conv(warped, ret_w) + ret_b, then GRU gates, write nh.
// 16x16 pixel tile, 128 threads (2 px/thread), 8 matched (r,u,m) channel
// triples per block. Weights read as float4 broadcasts (6 LDS.128 per ci
// instead of 24 LDS.32). Inputs streamed with 16-deep LDG batches (MLP).
// ---------------------------------------------------------------------------
__global__ __launch_bounds__(128)
void gate_k(const float* __restrict__ warped,
            const float* __restrict__ retw,
            const float* __restrict__ retb,
            const float* __restrict__ i2ht,   // base = g_i2h + (t*B)*192*HW (scrambled idx!)
            const float* __restrict__ prevh, int phBS,
            float* __restrict__ outb, int outBS)
{
    __shared__ __align__(16) float s_w[320*24];
    const int b = blockIdx.z >> 3;
    const int g = blockIdx.z & 7;
    const int tx = threadIdx.x & 15;
    const int ty = threadIdx.x >> 4;
    const int x = blockIdx.x*16 + tx;
    const int y = blockIdx.y*16 + ty;

    for (int i = threadIdx.x; i < 320*24; i += 128) {
        int ci = i / 24, j = i - ci*24;
        int co = (j >> 3)*64 + g*8 + (j & 7);   // j<8: r-set, j<16: u-set, else m-set
        s_w[i] = retw[(size_t)co*320 + ci];
    }
    __syncthreads();

    float acc0[24], acc1[24];
#pragma unroll
    for (int j = 0; j < 24; j++){ acc0[j] = 0.f; acc1[j] = 0.f; }

    const int p0 = y*W + x, p1 = p0 + 8*W;
    const float* wp = warped + (size_t)b*(320*HW);
    for (int ci0 = 0; ci0 < 320; ci0 += 8) {
        float v0[8], v1[8];
#pragma unroll
        for (int q = 0; q < 8; q++) {
            v0[q] = __ldg(wp + (size_t)(ci0+q)*HW + p0);
            v1[q] = __ldg(wp + (size_t)(ci0+q)*HW + p1);
        }
#pragma unroll
        for (int q = 0; q < 8; q++) {
            const float4* w4 = reinterpret_cast<const float4*>(s_w + (ci0+q)*24);
#pragma unroll
            for (int j4 = 0; j4 < 6; j4++) {
                float4 wv = w4[j4];               // 16B broadcast, 1 slot
                acc0[4*j4+0] += v0[q]*wv.x;  acc1[4*j4+0] += v1[q]*wv.x;
                acc0[4*j4+1] += v0[q]*wv.y;  acc1[4*j4+1] += v1[q]*wv.y;
                acc0[4*j4+2] += v0[q]*wv.z;  acc1[4*j4+2] += v1[q]*wv.z;
                acc0[4*j4+3] += v0[q]*wv.w;  acc1[4*j4+3] += v1[q]*wv.w;
            }
        }
    }

    const float* ib = i2ht  + (size_t)b*(192*HW);
    const float* ph = prevh + (size_t)b*phBS;
    float* ob = outb + (size_t)b*outBS;

#pragma unroll
    for (int i = 0; i < 8; i++) {
        int co = g*8 + i;
        float br = retb[co], bu = retb[64+co], bm = retb[128+co];
        {   // pixel 0
            float hr = acc0[i] + br, hu = acc0[8+i] + bu, hm = acc0[16+i] + bm;
            float r = 1.f/(1.f + expf(-(ib[(size_t)co*HW       + p0] + hr)));
            float u = 1.f/(1.f + expf(-(ib[(size_t)(64+co)*HW  + p0] + hu)));
            float m = tanhf(        ib[(size_t)(128+co)*HW + p0] + r*hm);
            float pv = ph[(size_t)co*HW + p0];
            ob[(size_t)co*HW + p0] = u*pv + (1.f - u)*m;
        }
        {   // pixel 1
            float hr = acc1[i] + br, hu = acc1[8+i] + bu, hm = acc1[16+i] + bm;
            float r = 1.f/(1.f + expf(-(ib[(size_t)co*HW       + p1] + hr)));
            float u = 1.f/(1.f + expf(-(ib[(size_t)(64+co)*HW  + p1] + hu)));
            float m = tanhf(        ib[(size_t)(128+co)*HW + p1] + r*hm);
            float pv = ph[(size_t)co*HW + p1];
            ob[(size_t)co*HW + p1] = u*pv + (1.f - u)*m;
        }
    }
}

// last_h = outs[:, T-1]
__global__ void copy_last(float* __restrict__ out)
{
    int i = blockIdx.x*blockDim.x + threadIdx.x;
    if (i >= B*CO*HW) return;
    int b = i / (CO*HW);
    int r = i - b*(CO*HW);
    out[(size_t)B*T*CO*HW + i] = out[((size_t)(b*T + (T-1))*CO)*HW + r];
}

// ---------------------------------------------------------------------------
extern "C" void kernel_launch(void* const* d_in, const int* in_sizes, int n_in,
                              void* d_out, int out_size)
{
    const float* inputs  = (const float*)d_in[0];
    const float* i2h_w   = (const float*)d_in[1];
    const float* i2h_b   = (const float*)d_in[2];
    const float* i2f_w   = (const float*)d_in[3];
    const float* i2f_b   = (const float*)d_in[4];
    const float* h2f_w   = (const float*)d_in[5];
    const float* h2f_b   = (const float*)d_in[6];
    const float* flows_w = (const float*)d_in[7];
    const float* flows_b = (const float*)d_in[8];
    const float* ret_w   = (const float*)d_in[9];
    const float* ret_b   = (const float*)d_in[10];
    float* out = (float*)d_out;
    (void)in_sizes; (void)n_in; (void)out_size;

    float *p_i2h, *p_i2f, *p_f1, *p_flows, *p_warped, *p_zero;
    cudaGetSymbolAddress((void**)&p_i2h,    g_i2h);
    cudaGetSymbolAddress((void**)&p_i2f,    g_i2f);
    cudaGetSymbolAddress((void**)&p_f1,     g_f1);
    cudaGetSymbolAddress((void**)&p_flows,  g_flows);
    cudaGetSymbolAddress((void**)&p_warped, g_warped);
    cudaGetSymbolAddress((void**)&p_zero,   g_zero);

    // One-time host resources (streams/events, no device memory). Device work
    // per call is identical and deterministic.
    static cudaStream_t s2 = nullptr;
    static cudaEvent_t  evFork = nullptr;
    static cudaEvent_t  evI2f[T], evI2h[T];
    static bool ok2 = false;
    if (s2 == nullptr) {
        bool good = (cudaStreamCreateWithFlags(&s2, cudaStreamNonBlocking) == cudaSuccess);
        good = good && (cudaEventCreateWithFlags(&evFork, cudaEventDisableTiming) == cudaSuccess);
        for (int t = 0; t < T && good; t++) {
            good = good && (cudaEventCreateWithFlags(&evI2f[t], cudaEventDisableTiming) == cudaSuccess);
            good = good && (cudaEventCreateWithFlags(&evI2h[t], cudaEventDisableTiming) == cudaSuccess);
        }
        ok2 = good;
    }

    cudaStream_t sp = 0;   // precompute stream (forked if available)
    if (ok2) {
        cudaEventRecord(evFork, 0);
        cudaStreamWaitEvent(s2, evFork, 0);
        sp = s2;
    }

    // Precompute, chunked per consumer timestep, on the forked stream.
    //  i2f chunk t: images m = b*T + t  (consumed by h2f at step t)
    //  i2h chunk t: images m = t*B + b  (consumed by gate at step t; this IS
    //               the reference's reshape(B*T)->reshape(T,B) scramble)
    // Tile grid: x = 96/32 = 3, y = 96/8 = 12.
    for (int t = 0; t < T; t++) {
        conv2d_k<5,16,false,1><<<dim3(3,12,B*2), 128, 0, sp>>>(
            inputs, CIN*HW, i2f_w, i2f_b, nullptr, 0,
            p_i2f, 32*HW, CIN, 32, /*nBase=*/t, /*nStep=*/T);
        if (ok2) cudaEventRecord(evI2f[t], s2);

        conv2d_k<3,16,false,1><<<dim3(3,12,B*12), 128, 0, sp>>>(
            inputs, CIN*HW, i2h_w, i2h_b, nullptr, 0,
            p_i2h, 3*CO*HW, CIN, 3*CO, /*nBase=*/t*B, /*nStep=*/1);
        if (ok2) cudaEventRecord(evI2h[t], s2);
    }

    for (int t = 0; t < T; t++) {
        const float* prevh = (t == 0) ? p_zero : out + (size_t)(t-1)*CO*HW;
        int phBS = (t == 0) ? CO*HW : T*CO*HW;

        if (ok2) cudaStreamWaitEvent(0, evI2f[t], 0);

        // f1 = tanh(i2f[b,t] + conv5x5(prev_h, h2f_w) + h2f_b)   [Cin split x2]
        conv2d_k<5,16,true,2><<<dim3(3,12,B*2), 256>>>(
            prevh, phBS, h2f_w, h2f_b,
            p_i2f + (size_t)t*32*HW, T*32*HW,
            p_f1, 32*HW, CO, 32, 0, 1);

        // flows = conv5x5(f1, flows_w) + flows_b   -> (B, L*2, H, W)  [Cin split x4]
        conv2d_k<5,10,false,4><<<dim3(3,12,B), 512>>>(
            p_f1, 32*HW, flows_w, flows_b, nullptr, 0,
            p_flows, 2*L*HW, 32, 2*L, 0, 1);

        // warped(B, L*CO, H, W)
        warp_k<<<(B*L*HW + 255)/256, 256>>>(prevh, phBS, p_flows, p_warped);

        if (ok2) cudaStreamWaitEvent(0, evI2h[t], 0);

        // h2h (1x1, 320->192) + GRU gates -> nh written to out[:, t]
        gate_k<<<dim3(6,6,B*8), 128>>>(
            p_warped, ret_w, ret_b,
            p_i2h + (size_t)(t*B)*3*CO*HW,
            prevh, phBS,
            out + (size_t)t*CO*HW, T*CO*HW);
    }

    copy_last<<<(B*CO*HW + 255)/256, 256>>>(out);
}